// round 1
// baseline (speedup 1.0000x reference)
#include <cuda_runtime.h>
#include <cstdint>
#include <math.h>

#define B_   2
#define S_   2048
#define D_   2048
#define Lh_  3
#define H_   16
#define DH_  128
#define BLK_ 16
#define NA_  64
#define Q_   1024
#define KV_  3072
#define V_   32000
#define MASKID_ 31999

// ---------------- scratch (static device globals; no allocation) ----------------
__device__ float g_ctxcat[(size_t)B_*S_*Lh_*D_];   // 100.7 MB
__device__ float g_ctx   [(size_t)B_*S_*D_];
__device__ float g_emb   [(size_t)B_*Q_*D_];
__device__ float g_xkv   [(size_t)B_*KV_*D_];
__device__ float g_q     [(size_t)B_*Q_*D_];
__device__ float g_k     [(size_t)B_*KV_*D_];
__device__ float g_v     [(size_t)B_*KV_*D_];
__device__ float g_ao    [(size_t)B_*Q_*D_];
__device__ float g_op    [(size_t)B_*Q_*D_];
__device__ float g_hid   [(size_t)B_*Q_*D_];
__device__ float g_logits[(size_t)B_*Q_*V_];       // 262 MB
__device__ float g_part  [B_*Q_*4];

// ---------------- pack: hidden_states (L,B,S,D) -> ctx_cat (B,S,L*D) ----------------
__global__ void k_pack_ctxcat(const float* __restrict__ hs) {
    int gid = blockIdx.x * blockDim.x + threadIdx.x;      // float4 index
    const int total = B_*S_*Lh_*D_/4;
    if (gid >= total) return;
    int dd = gid & 511;           // D/4 = 512
    int x  = gid >> 9;
    int l  = x % 3; x /= 3;
    int s  = x & 2047;
    int b  = x >> 11;
    const float4* src = (const float4*)hs + (((size_t)((l*B_ + b)*S_ + s)) << 9) + dd;
    ((float4*)g_ctxcat)[gid] = *src;
}

// ---------------- emb = embed_table[draft_ids] ----------------
__global__ void k_emb(const int* __restrict__ ids, const int* __restrict__ anc,
                      const float* __restrict__ et) {
    int gid = blockIdx.x * blockDim.x + threadIdx.x;      // float4 index
    const int total = B_*Q_*D_/4;
    if (gid >= total) return;
    int dd  = gid & 511;
    int tok = gid >> 9;
    int b   = tok >> 10;
    int qi  = tok & 1023;
    int off = qi & 15;
    int id  = MASKID_;
    if (off == 0) id = ids[b*S_ + anc[b*NA_ + (qi >> 4)]];
    ((float4*)g_emb)[gid] = ((const float4*)et)[(((size_t)id) << 9) + dd];
}

// ---------------- x_kv = concat(ctx, emb) ----------------
__global__ void k_xkv() {
    int gid = blockIdx.x * blockDim.x + threadIdx.x;
    const int total = B_*KV_*D_/4;
    if (gid >= total) return;
    int dd  = gid & 511;
    int tok = gid >> 9;
    int b   = tok / KV_;
    int r   = tok - b*KV_;
    float4 val;
    if (r < S_) val = ((const float4*)g_ctx)[(((size_t)(b*S_ + r)) << 9) + dd];
    else        val = ((const float4*)g_emb)[(((size_t)(b*Q_ + (r - S_))) << 9) + dd];
    ((float4*)g_xkv)[gid] = val;
}

// ---------------- SGEMM: C[M,N] = A[M,K] @ W[N,K]^T ; M,N %128==0, K %8==0 ----------------
#define BM 128
#define BN 128
#define BK 8
__global__ __launch_bounds__(256) void k_sgemm_nt(const float* __restrict__ A,
                                                  const float* __restrict__ W,
                                                  float* __restrict__ C,
                                                  int M, int N, int K) {
    __shared__ float As[BK][BM];
    __shared__ float Bs[BK][BN];
    int bx = blockIdx.x, by = blockIdx.y;
    int t  = threadIdx.x;
    int tx = t & 15, ty = t >> 4;
    int lrow = t >> 1;
    int lk   = (t & 1) * 4;
    const float* Ab = A + (size_t)(by * BM) * K;
    const float* Wb = W + (size_t)(bx * BN) * K;
    float acc[8][8];
#pragma unroll
    for (int i = 0; i < 8; i++)
#pragma unroll
        for (int j = 0; j < 8; j++) acc[i][j] = 0.f;

    for (int k0 = 0; k0 < K; k0 += BK) {
        float4 a4 = *(const float4*)(Ab + (size_t)lrow * K + k0 + lk);
        float4 b4 = *(const float4*)(Wb + (size_t)lrow * K + k0 + lk);
        As[lk+0][lrow] = a4.x; As[lk+1][lrow] = a4.y; As[lk+2][lrow] = a4.z; As[lk+3][lrow] = a4.w;
        Bs[lk+0][lrow] = b4.x; Bs[lk+1][lrow] = b4.y; Bs[lk+2][lrow] = b4.z; Bs[lk+3][lrow] = b4.w;
        __syncthreads();
#pragma unroll
        for (int kk = 0; kk < BK; kk++) {
            float4 a0 = *(const float4*)&As[kk][ty*8];
            float4 a1 = *(const float4*)&As[kk][ty*8+4];
            float4 b0 = *(const float4*)&Bs[kk][tx*8];
            float4 b1 = *(const float4*)&Bs[kk][tx*8+4];
            float ar[8] = {a0.x,a0.y,a0.z,a0.w,a1.x,a1.y,a1.z,a1.w};
            float br[8] = {b0.x,b0.y,b0.z,b0.w,b1.x,b1.y,b1.z,b1.w};
#pragma unroll
            for (int i = 0; i < 8; i++)
#pragma unroll
                for (int j = 0; j < 8; j++) acc[i][j] += ar[i] * br[j];
        }
        __syncthreads();
    }
#pragma unroll
    for (int i = 0; i < 8; i++) {
        size_t row = (size_t)(by*BM + ty*8 + i);
        float4 c0 = {acc[i][0],acc[i][1],acc[i][2],acc[i][3]};
        float4 c1 = {acc[i][4],acc[i][5],acc[i][6],acc[i][7]};
        *(float4*)(C + row*N + bx*BN + tx*8)     = c0;
        *(float4*)(C + row*N + bx*BN + tx*8 + 4) = c1;
    }
}

// ---------------- RoPE (in-place). mode 0: q tokens; mode 1: kv tokens ----------------
__global__ void k_rope(float* __restrict__ buf, const int* __restrict__ anc,
                       int T, int mode) {
    int gid = blockIdx.x * blockDim.x + threadIdx.x;
    int total = T * H_ * 64;
    if (gid >= total) return;
    int i   = gid & 63;
    int x   = gid >> 6;
    int h   = x & 15;
    int tok = x >> 4;
    int pos;
    if (mode == 0) {
        int b = tok >> 10, qi = tok & 1023;
        pos = anc[b*NA_ + (qi >> 4)] + (qi & 15);
    } else {
        int b = tok / KV_;
        int r = tok - b*KV_;
        pos = (r < S_) ? r : anc[b*NA_ + ((r - S_) >> 4)] + ((r - S_) & 15);
    }
    float invf = (float)exp(-9.210340371976184 * (double)i / 64.0); // 10000^{-i/64}
    float ang  = (float)pos * invf;
    float c = cosf(ang), s = sinf(ang);
    float* p = buf + (size_t)tok * D_ + h * DH_;
    float x1 = p[i], x2 = p[i + 64];
    p[i]      = x1 * c - x2 * s;
    p[i + 64] = x2 * c + x1 * s;
}

// ---------------- attention (flash-style, 64x64 tiles, fp32) ----------------
#define SD 132   // padded row stride for Q/K/V tiles
#define PS 68    // padded row stride for score tile
#define ATTN_SMEM ((3*64*SD + 64*PS + 192) * 4)
__global__ __launch_bounds__(256) void k_attn(const float* __restrict__ q,
                                              const float* __restrict__ k,
                                              const float* __restrict__ v,
                                              const int* __restrict__ anc,
                                              float* __restrict__ o) {
    extern __shared__ float sm[];
    float* Qs = sm;
    float* Ks = Qs + 64*SD;
    float* Vs = Ks + 64*SD;
    float* Ps = Vs + 64*SD;
    float* sm_m = Ps + 64*PS;
    float* sm_l = sm_m + 64;
    float* sm_c = sm_l + 64;
    __shared__ int s_apos[4];

    int qt = blockIdx.x;     // 0..15
    int h  = blockIdx.y;     // 0..15
    int b  = blockIdx.z;     // 0..1
    int t  = threadIdx.x;
    int ty = t >> 4, tx = t & 15;

    if (t < 4) s_apos[t] = anc[b*NA_ + qt*4 + t];
    const float scale = 0.08838834764831845f;  // 1/sqrt(128)
    size_t qbase = ((size_t)b*Q_ + qt*64) * D_ + h*DH_;
    for (int i = t; i < 64*32; i += 256) {
        int r = i >> 5, dq = (i & 31) * 4;
        float4 val = *(const float4*)(q + qbase + (size_t)r*D_ + dq);
        val.x *= scale; val.y *= scale; val.z *= scale; val.w *= scale;
        *(float4*)(Qs + r*SD + dq) = val;
    }
    if (t < 64) { sm_m[t] = -1e30f; sm_l[t] = 0.f; }
    __syncthreads();

    int maxap = max(max(s_apos[0], s_apos[1]), max(s_apos[2], s_apos[3]));
    int nctx  = (maxap + 63) >> 6;   // #context tiles with any visible key

    float acc[4][8];
#pragma unroll
    for (int i = 0; i < 4; i++)
#pragma unroll
        for (int j = 0; j < 8; j++) acc[i][j] = 0.f;

    for (int it = 0; it <= nctx; it++) {
        int kv0 = (it < nctx) ? it*64 : S_ + qt*64;   // last iter = draft tile
        // load K,V tiles
        for (int i = t; i < 64*32; i += 256) {
            int r = i >> 5, dq = (i & 31) * 4;
            size_t g = ((size_t)b*KV_ + kv0 + r) * D_ + h*DH_ + dq;
            *(float4*)(Ks + r*SD + dq) = *(const float4*)(k + g);
            *(float4*)(Vs + r*SD + dq) = *(const float4*)(v + g);
        }
        __syncthreads();

        // scores: 4x4 microtile per thread
        float sreg[4][4];
#pragma unroll
        for (int i = 0; i < 4; i++)
#pragma unroll
            for (int j = 0; j < 4; j++) sreg[i][j] = 0.f;
        for (int d = 0; d < DH_; d += 4) {
            float4 qv[4], kv4[4];
#pragma unroll
            for (int i = 0; i < 4; i++) qv[i]  = *(const float4*)(Qs + (ty*4+i)*SD + d);
#pragma unroll
            for (int j = 0; j < 4; j++) kv4[j] = *(const float4*)(Ks + (tx*4+j)*SD + d);
#pragma unroll
            for (int i = 0; i < 4; i++)
#pragma unroll
                for (int j = 0; j < 4; j++)
                    sreg[i][j] += qv[i].x*kv4[j].x + qv[i].y*kv4[j].y
                                + qv[i].z*kv4[j].z + qv[i].w*kv4[j].w;
        }
        // mask + store to Ps
#pragma unroll
        for (int i = 0; i < 4; i++) {
            int r  = ty*4 + i;
            int qg = qt*64 + r;
            int qb = qg >> 4;
            int ap = s_apos[r >> 4];
#pragma unroll
            for (int j = 0; j < 4; j++) {
                int kk = kv0 + tx*4 + j;
                bool vis = (kk < S_) ? (kk < ap) : (((kk - S_) >> 4) == qb);
                Ps[r*PS + tx*4 + j] = vis ? sreg[i][j] : -1e30f;
            }
        }
        __syncthreads();

        // online softmax row update (one thread per row)
        if (t < 64) {
            float m_old = sm_m[t];
            float mt = m_old;
            for (int j = 0; j < 64; j++) mt = fmaxf(mt, Ps[t*PS + j]);
            float c = __expf(m_old - mt);
            float rs = 0.f;
            for (int j = 0; j < 64; j++) {
                float sv = Ps[t*PS + j];
                float p  = (sv < -9e29f) ? 0.f : __expf(sv - mt);
                Ps[t*PS + j] = p;
                rs += p;
            }
            sm_m[t] = mt;
            sm_l[t] = sm_l[t] * c + rs;
            sm_c[t] = c;
        }
        __syncthreads();

        // o update: thread owns rows ty*4..+3, dh tx*8..+7
#pragma unroll
        for (int i = 0; i < 4; i++) {
            float c = sm_c[ty*4 + i];
#pragma unroll
            for (int j = 0; j < 8; j++) acc[i][j] *= c;
        }
        for (int j = 0; j < 64; j++) {
            float4 v0 = *(const float4*)(Vs + j*SD + tx*8);
            float4 v1 = *(const float4*)(Vs + j*SD + tx*8 + 4);
#pragma unroll
            for (int i = 0; i < 4; i++) {
                float p = Ps[(ty*4+i)*PS + j];
                acc[i][0] += p*v0.x; acc[i][1] += p*v0.y;
                acc[i][2] += p*v0.z; acc[i][3] += p*v0.w;
                acc[i][4] += p*v1.x; acc[i][5] += p*v1.y;
                acc[i][6] += p*v1.z; acc[i][7] += p*v1.w;
            }
        }
        __syncthreads();
    }

#pragma unroll
    for (int i = 0; i < 4; i++) {
        int r = ty*4 + i;
        float inv_l = 1.f / sm_l[r];
        size_t ob = ((size_t)b*Q_ + qt*64 + r) * D_ + h*DH_ + tx*8;
        float4 o0 = {acc[i][0]*inv_l, acc[i][1]*inv_l, acc[i][2]*inv_l, acc[i][3]*inv_l};
        float4 o1 = {acc[i][4]*inv_l, acc[i][5]*inv_l, acc[i][6]*inv_l, acc[i][7]*inv_l};
        *(float4*)(o + ob)     = o0;
        *(float4*)(o + ob + 4) = o1;
    }
}

// ---------------- hidden = rmsnorm(emb + oproj) * norm_weight ----------------
__global__ void k_addnorm(const float* __restrict__ nw) {
    int row = blockIdx.x;
    int t   = threadIdx.x;
    const float* e = g_emb + (size_t)row * D_;
    const float* o = g_op  + (size_t)row * D_;
    float ss = 0.f;
    for (int d = t; d < D_; d += 256) { float h = e[d] + o[d]; ss += h * h; }
    __shared__ float red[256];
    red[t] = ss; __syncthreads();
    for (int st = 128; st; st >>= 1) { if (t < st) red[t] += red[t + st]; __syncthreads(); }
    float inv = rsqrtf(red[0] / (float)D_ + 1e-6f);
    for (int d = t; d < D_; d += 256)
        g_hid[(size_t)row * D_ + d] = (e[d] + o[d]) * inv * nw[d];
}

// ---------------- per-token logsumexp + argmax + nll ----------------
__global__ void k_loss(const int* __restrict__ ids, const int* __restrict__ anc) {
    int row = blockIdx.x;            // 0..2047
    int b = row >> 10, qi = row & 1023;
    int off = qi & 15;
    if (off == 0) {
        if (threadIdx.x == 0) {
            g_part[row*4+0] = 0.f; g_part[row*4+1] = 0.f;
            g_part[row*4+2] = 0.f; g_part[row*4+3] = 0.f;
        }
        return;
    }
    int anchor = anc[b*NA_ + (qi >> 4)];
    int label  = ids[b*S_ + anchor + off];
    const float* L = g_logits + (size_t)row * V_;
    int t = threadIdx.x;
    float m = -1e30f, s = 0.f, bm = -1e30f;
    int bi = 0;
    for (int vv = t; vv < V_; vv += 256) {
        float x = L[vv];
        if (x > m) { s = s * expf(m - x) + 1.f; m = x; }
        else       { s += expf(x - m); }
        if (x > bm || (x == bm && vv < bi)) { bm = x; bi = vv; }
    }
    __shared__ float rm[256], rs[256], rbm[256];
    __shared__ int rbi[256];
    rm[t] = m; rs[t] = s; rbm[t] = bm; rbi[t] = bi;
    __syncthreads();
    for (int st = 128; st; st >>= 1) {
        if (t < st) {
            float m2 = rm[t+st], s2 = rs[t+st];
            float M = fmaxf(rm[t], m2);
            rs[t] = rs[t]*expf(rm[t]-M) + s2*expf(m2-M);
            rm[t] = M;
            float b2 = rbm[t+st]; int i2 = rbi[t+st];
            if (b2 > rbm[t] || (b2 == rbm[t] && i2 < rbi[t])) { rbm[t] = b2; rbi[t] = i2; }
        }
        __syncthreads();
    }
    if (t == 0) {
        float lse = rm[0] + logf(rs[0]);
        float nll = lse - L[label];
        float w   = expf(-(float)(off - 1) / 7.0f);
        g_part[row*4+0] = nll * w;
        g_part[row*4+1] = w;
        g_part[row*4+2] = (rbi[0] == label) ? 1.f : 0.f;
        g_part[row*4+3] = 1.f;
    }
}

// ---------------- final scalar reduction ----------------
__global__ void k_final(float* __restrict__ out) {
    int t = threadIdx.x;
    float a = 0.f, bw = 0.f, c = 0.f, d = 0.f;
    for (int r = t; r < B_*Q_; r += 256) {
        a  += g_part[r*4+0];
        bw += g_part[r*4+1];
        c  += g_part[r*4+2];
        d  += g_part[r*4+3];
    }
    __shared__ float s0[256], s1[256], s2[256], s3[256];
    s0[t]=a; s1[t]=bw; s2[t]=c; s3[t]=d;
    __syncthreads();
    for (int st = 128; st; st >>= 1) {
        if (t < st) { s0[t]+=s0[t+st]; s1[t]+=s1[t+st]; s2[t]+=s2[t+st]; s3[t]+=s3[t+st]; }
        __syncthreads();
    }
    if (t == 0) {
        out[0] = s0[0] / fmaxf(s1[0], 1e-6f);
        out[1] = s2[0] / fmaxf(s3[0], 1.0f);
    }
}

// ---------------- launch ----------------
extern "C" void kernel_launch(void* const* d_in, const int* in_sizes, int n_in,
                              void* d_out, int out_size) {
    const int*   ids     = (const int*)  d_in[0];
    const float* hs      = (const float*)d_in[1];
    // d_in[2] loss_mask — unused by reference
    const float* lm_head = (const float*)d_in[3];
    const float* norm_w  = (const float*)d_in[4];
    const int*   anc     = (const int*)  d_in[5];
    const float* ctx_w   = (const float*)d_in[6];
    const float* embed   = (const float*)d_in[7];
    const float* wq      = (const float*)d_in[8];
    const float* wk      = (const float*)d_in[9];
    const float* wv      = (const float*)d_in[10];
    const float* wo      = (const float*)d_in[11];
    float* out = (float*)d_out;

    void *p;
    cudaGetSymbolAddress(&p, g_ctxcat); float* ctxcat = (float*)p;
    cudaGetSymbolAddress(&p, g_ctx);    float* ctx    = (float*)p;
    cudaGetSymbolAddress(&p, g_emb);    float* emb    = (float*)p;
    cudaGetSymbolAddress(&p, g_xkv);    float* xkv    = (float*)p;
    cudaGetSymbolAddress(&p, g_q);      float* qb     = (float*)p;
    cudaGetSymbolAddress(&p, g_k);      float* kb     = (float*)p;
    cudaGetSymbolAddress(&p, g_v);      float* vb     = (float*)p;
    cudaGetSymbolAddress(&p, g_ao);     float* ao     = (float*)p;
    cudaGetSymbolAddress(&p, g_op);     float* op     = (float*)p;
    cudaGetSymbolAddress(&p, g_hid);    float* hid    = (float*)p;
    cudaGetSymbolAddress(&p, g_logits); float* logits = (float*)p;

    cudaFuncSetAttribute(k_attn, cudaFuncAttributeMaxDynamicSharedMemorySize, ATTN_SMEM);

    // 1. pack ctx_cat
    k_pack_ctxcat<<<(B_*S_*Lh_*D_/4 + 255)/256, 256>>>(hs);
    // 2. embedding gather
    k_emb<<<(B_*Q_*D_/4 + 255)/256, 256>>>(ids, anc, embed);
    // 3. ctx projection
    k_sgemm_nt<<<dim3(D_/BN, B_*S_/BM), 256>>>(ctxcat, ctx_w, ctx, B_*S_, D_, Lh_*D_);
    // 4. x_kv pack
    k_xkv<<<(B_*KV_*D_/4 + 255)/256, 256>>>();
    // 5. q projection + rope
    k_sgemm_nt<<<dim3(D_/BN, B_*Q_/BM), 256>>>(emb, wq, qb, B_*Q_, D_, D_);
    k_rope<<<(B_*Q_*H_*64 + 255)/256, 256>>>(qb, anc, B_*Q_, 0);
    // 6. k projection + rope
    k_sgemm_nt<<<dim3(D_/BN, B_*KV_/BM), 256>>>(xkv, wk, kb, B_*KV_, D_, D_);
    k_rope<<<(B_*KV_*H_*64 + 255)/256, 256>>>(kb, anc, B_*KV_, 1);
    // 7. v projection
    k_sgemm_nt<<<dim3(D_/BN, B_*KV_/BM), 256>>>(xkv, wv, vb, B_*KV_, D_, D_);
    // 8. attention
    k_attn<<<dim3(Q_/64, H_, B_), 256, ATTN_SMEM>>>(qb, kb, vb, anc, ao);
    // 9. output projection
    k_sgemm_nt<<<dim3(D_/BN, B_*Q_/BM), 256>>>(ao, wo, op, B_*Q_, D_, D_);
    // 10. residual + rmsnorm
    k_addnorm<<<B_*Q_, 256>>>(norm_w);
    // 11. lm_head
    k_sgemm_nt<<<dim3(V_/BN, B_*Q_/BM), 256>>>(hid, lm_head, logits, B_*Q_, V_, D_);
    // 12. per-token loss
    k_loss<<<B_*Q_, 256>>>(ids, anc);
    // 13. final scalars
    k_final<<<1, 256>>>(out);
}

// round 4
// speedup vs baseline: 3.4671x; 3.4671x over previous
#include <cuda_runtime.h>
#include <cstdint>
#include <math.h>

#define B_   2
#define S_   2048
#define D_   2048
#define Lh_  3
#define H_   16
#define DH_  128
#define BLK_ 16
#define NA_  64
#define Q_   1024
#define KV_  3072
#define V_   32000
#define MASKID_ 31999

// ---------------- scratch (static device globals; no allocation) ----------------
__device__ float g_ctxcat[(size_t)B_*S_*Lh_*D_];   // 100.7 MB
__device__ float g_ctx   [(size_t)B_*S_*D_];
__device__ float g_emb   [(size_t)B_*Q_*D_];
__device__ float g_xkv   [(size_t)B_*KV_*D_];
__device__ float g_q     [(size_t)B_*Q_*D_];
__device__ float g_k     [(size_t)B_*KV_*D_];
__device__ float g_v     [(size_t)B_*KV_*D_];
__device__ float g_ao    [(size_t)B_*Q_*D_];
__device__ float g_op    [(size_t)B_*Q_*D_];
__device__ float g_hid   [(size_t)B_*Q_*D_];
__device__ float g_logits[(size_t)B_*Q_*V_];       // 262 MB
__device__ float g_part  [B_*Q_*4];

// ---------------- pack: hidden_states (L,B,S,D) -> ctx_cat (B,S,L*D) ----------------
__global__ void k_pack_ctxcat(const float* __restrict__ hs) {
    int gid = blockIdx.x * blockDim.x + threadIdx.x;      // float4 index
    const int total = B_*S_*Lh_*D_/4;
    if (gid >= total) return;
    int dd = gid & 511;           // D/4 = 512
    int x  = gid >> 9;
    int l  = x % 3; x /= 3;
    int s  = x & 2047;
    int b  = x >> 11;
    const float4* src = (const float4*)hs + (((size_t)((l*B_ + b)*S_ + s)) << 9) + dd;
    ((float4*)g_ctxcat)[gid] = *src;
}

// ---------------- emb = embed_table[draft_ids] ----------------
__global__ void k_emb(const int* __restrict__ ids, const int* __restrict__ anc,
                      const float* __restrict__ et) {
    int gid = blockIdx.x * blockDim.x + threadIdx.x;      // float4 index
    const int total = B_*Q_*D_/4;
    if (gid >= total) return;
    int dd  = gid & 511;
    int tok = gid >> 9;
    int b   = tok >> 10;
    int qi  = tok & 1023;
    int off = qi & 15;
    int id  = MASKID_;
    if (off == 0) id = ids[b*S_ + anc[b*NA_ + (qi >> 4)]];
    ((float4*)g_emb)[gid] = ((const float4*)et)[(((size_t)id) << 9) + dd];
}

// ---------------- x_kv = concat(ctx, emb) ----------------
__global__ void k_xkv() {
    int gid = blockIdx.x * blockDim.x + threadIdx.x;
    const int total = B_*KV_*D_/4;
    if (gid >= total) return;
    int dd  = gid & 511;
    int tok = gid >> 9;
    int b   = tok / KV_;
    int r   = tok - b*KV_;
    float4 val;
    if (r < S_) val = ((const float4*)g_ctx)[(((size_t)(b*S_ + r)) << 9) + dd];
    else        val = ((const float4*)g_emb)[(((size_t)(b*Q_ + (r - S_))) << 9) + dd];
    ((float4*)g_xkv)[gid] = val;
}

// ---------------- TF32 tensor-core GEMM: C[M,N] = A[M,K] @ W[N,K]^T ----------------
// 128x128 block tile, BK=16, 8 warps in 2(m) x 4(n), warp tile 64x32.
// Shared stride SP=136 (== 8 mod 32) -> conflict-free fragment reads.
#define BM 128
#define BN 128
#define BK 16
#define SP 136

__device__ __forceinline__ uint32_t f2tf(float x) {
    uint32_t r; asm("cvt.rna.tf32.f32 %0, %1;" : "=r"(r) : "f"(x)); return r;
}

__device__ __forceinline__ void mma_tf32(float* c, const uint32_t* a, const uint32_t* b) {
    asm volatile(
        "mma.sync.aligned.m16n8k8.row.col.f32.tf32.tf32.f32 "
        "{%0,%1,%2,%3},{%4,%5,%6,%7},{%8,%9},{%0,%1,%2,%3};"
        : "+f"(c[0]), "+f"(c[1]), "+f"(c[2]), "+f"(c[3])
        : "r"(a[0]), "r"(a[1]), "r"(a[2]), "r"(a[3]), "r"(b[0]), "r"(b[1]));
}

__global__ __launch_bounds__(256) void k_mma_nt(const float* __restrict__ A,
                                                const float* __restrict__ W,
                                                float* __restrict__ C,
                                                int M, int N, int K) {
    __shared__ uint32_t As[2][BK * SP];
    __shared__ uint32_t Bs[2][BK * SP];

    int bx = blockIdx.x, by = blockIdx.y;
    int t    = threadIdx.x;
    int lane = t & 31;
    int warp = t >> 5;
    int warpM = warp & 1;          // 0..1
    int warpN = warp >> 1;         // 0..3
    int mbase = warpM * 64;
    int nbase = warpN * 32;
    int grp = lane >> 2;           // 0..7
    int qd  = lane & 3;            // 0..3

    int lrow = t >> 1;             // 0..127
    int lkc  = (t & 1) * 8;        // 0 or 8
    const float* Ab = A + (size_t)(by * BM + lrow) * K + lkc;
    const float* Wb = W + (size_t)(bx * BN + lrow) * K + lkc;

    float acc[4][4][4];
#pragma unroll
    for (int i = 0; i < 4; i++)
#pragma unroll
        for (int j = 0; j < 4; j++)
#pragma unroll
            for (int r = 0; r < 4; r++) acc[i][j][r] = 0.f;

    float4 ra0, ra1, rb0, rb1;
    // prologue: load tile 0
    ra0 = *(const float4*)(Ab + 0); ra1 = *(const float4*)(Ab + 4);
    rb0 = *(const float4*)(Wb + 0); rb1 = *(const float4*)(Wb + 4);
#pragma unroll
    for (int s = 0; s < 4; s++) {
        As[0][(lkc + s)*SP + lrow]     = f2tf(((float*)&ra0)[s]);
        As[0][(lkc + 4 + s)*SP + lrow] = f2tf(((float*)&ra1)[s]);
        Bs[0][(lkc + s)*SP + lrow]     = f2tf(((float*)&rb0)[s]);
        Bs[0][(lkc + 4 + s)*SP + lrow] = f2tf(((float*)&rb1)[s]);
    }
    __syncthreads();

    int ntiles = K / BK;
    int buf = 0;
    for (int it = 1; it <= ntiles; it++) {
        if (it < ntiles) {
            const float* Ap = Ab + it * BK;
            const float* Wp = Wb + it * BK;
            ra0 = *(const float4*)(Ap + 0); ra1 = *(const float4*)(Ap + 4);
            rb0 = *(const float4*)(Wp + 0); rb1 = *(const float4*)(Wp + 4);
        }
        // compute on buf
        const uint32_t* Asb = As[buf];
        const uint32_t* Bsb = Bs[buf];
#pragma unroll
        for (int k8 = 0; k8 < BK; k8 += 8) {
            uint32_t af[4][4];
#pragma unroll
            for (int i = 0; i < 4; i++) {
                int mrow = mbase + i * 16 + grp;
                af[i][0] = Asb[(k8 + qd)*SP + mrow];
                af[i][1] = Asb[(k8 + qd)*SP + mrow + 8];
                af[i][2] = Asb[(k8 + 4 + qd)*SP + mrow];
                af[i][3] = Asb[(k8 + 4 + qd)*SP + mrow + 8];
            }
            uint32_t bf[4][2];
#pragma unroll
            for (int j = 0; j < 4; j++) {
                int ncol = nbase + j * 8 + grp;
                bf[j][0] = Bsb[(k8 + qd)*SP + ncol];
                bf[j][1] = Bsb[(k8 + 4 + qd)*SP + ncol];
            }
#pragma unroll
            for (int i = 0; i < 4; i++)
#pragma unroll
                for (int j = 0; j < 4; j++)
                    mma_tf32(acc[i][j], af[i], bf[j]);
        }
        if (it < ntiles) {
#pragma unroll
            for (int s = 0; s < 4; s++) {
                As[buf^1][(lkc + s)*SP + lrow]     = f2tf(((float*)&ra0)[s]);
                As[buf^1][(lkc + 4 + s)*SP + lrow] = f2tf(((float*)&ra1)[s]);
                Bs[buf^1][(lkc + s)*SP + lrow]     = f2tf(((float*)&rb0)[s]);
                Bs[buf^1][(lkc + 4 + s)*SP + lrow] = f2tf(((float*)&rb1)[s]);
            }
            __syncthreads();
            buf ^= 1;
        }
    }

    // epilogue
#pragma unroll
    for (int i = 0; i < 4; i++) {
        int r0 = by * BM + mbase + i * 16 + grp;
#pragma unroll
        for (int j = 0; j < 4; j++) {
            int c0 = bx * BN + nbase + j * 8 + qd * 2;
            float2 v01 = {acc[i][j][0], acc[i][j][1]};
            float2 v23 = {acc[i][j][2], acc[i][j][3]};
            *(float2*)(C + (size_t)r0 * N + c0)       = v01;
            *(float2*)(C + (size_t)(r0 + 8) * N + c0) = v23;
        }
    }
}

// ---------------- RoPE (in-place). mode 0: q tokens; mode 1: kv tokens ----------------
__global__ void k_rope(float* __restrict__ buf, const int* __restrict__ anc,
                       int T, int mode) {
    int gid = blockIdx.x * blockDim.x + threadIdx.x;
    int total = T * H_ * 64;
    if (gid >= total) return;
    int i   = gid & 63;
    int x   = gid >> 6;
    int h   = x & 15;
    int tok = x >> 4;
    int pos;
    if (mode == 0) {
        int b = tok >> 10, qi = tok & 1023;
        pos = anc[b*NA_ + (qi >> 4)] + (qi & 15);
    } else {
        int b = tok / KV_;
        int r = tok - b*KV_;
        pos = (r < S_) ? r : anc[b*NA_ + ((r - S_) >> 4)] + ((r - S_) & 15);
    }
    float invf = (float)exp(-9.210340371976184 * (double)i / 64.0); // 10000^{-i/64}
    float ang  = (float)pos * invf;
    float c = cosf(ang), s = sinf(ang);
    float* p = buf + (size_t)tok * D_ + h * DH_;
    float x1 = p[i], x2 = p[i + 64];
    p[i]      = x1 * c - x2 * s;
    p[i + 64] = x2 * c + x1 * s;
}

// ---------------- attention (flash-style, 64x64 tiles, fp32) ----------------
#define SD 132   // padded row stride for Q/K/V tiles
#define PS 68    // padded row stride for score tile
#define ATTN_SMEM ((3*64*SD + 64*PS + 192) * 4)
__global__ __launch_bounds__(256) void k_attn(const float* __restrict__ q,
                                              const float* __restrict__ k,
                                              const float* __restrict__ v,
                                              const int* __restrict__ anc,
                                              float* __restrict__ o) {
    extern __shared__ float sm[];
    float* Qs = sm;
    float* Ks = Qs + 64*SD;
    float* Vs = Ks + 64*SD;
    float* Ps = Vs + 64*SD;
    float* sm_m = Ps + 64*PS;
    float* sm_l = sm_m + 64;
    float* sm_c = sm_l + 64;
    __shared__ int s_apos[4];

    int qt = blockIdx.x;     // 0..15
    int h  = blockIdx.y;     // 0..15
    int b  = blockIdx.z;     // 0..1
    int t  = threadIdx.x;
    int ty = t >> 4, tx = t & 15;

    if (t < 4) s_apos[t] = anc[b*NA_ + qt*4 + t];
    const float scale = 0.08838834764831845f;  // 1/sqrt(128)
    size_t qbase = ((size_t)b*Q_ + qt*64) * D_ + h*DH_;
    for (int i = t; i < 64*32; i += 256) {
        int r = i >> 5, dq = (i & 31) * 4;
        float4 val = *(const float4*)(q + qbase + (size_t)r*D_ + dq);
        val.x *= scale; val.y *= scale; val.z *= scale; val.w *= scale;
        *(float4*)(Qs + r*SD + dq) = val;
    }
    if (t < 64) { sm_m[t] = -1e30f; sm_l[t] = 0.f; }
    __syncthreads();

    int maxap = max(max(s_apos[0], s_apos[1]), max(s_apos[2], s_apos[3]));
    int nctx  = (maxap + 63) >> 6;   // #context tiles with any visible key

    float acc[4][8];
#pragma unroll
    for (int i = 0; i < 4; i++)
#pragma unroll
        for (int j = 0; j < 8; j++) acc[i][j] = 0.f;

    for (int it = 0; it <= nctx; it++) {
        int kv0 = (it < nctx) ? it*64 : S_ + qt*64;   // last iter = draft tile
        // load K,V tiles
        for (int i = t; i < 64*32; i += 256) {
            int r = i >> 5, dq = (i & 31) * 4;
            size_t g = ((size_t)b*KV_ + kv0 + r) * D_ + h*DH_ + dq;
            *(float4*)(Ks + r*SD + dq) = *(const float4*)(k + g);
            *(float4*)(Vs + r*SD + dq) = *(const float4*)(v + g);
        }
        __syncthreads();

        // scores: 4x4 microtile per thread
        float sreg[4][4];
#pragma unroll
        for (int i = 0; i < 4; i++)
#pragma unroll
            for (int j = 0; j < 4; j++) sreg[i][j] = 0.f;
        for (int d = 0; d < DH_; d += 4) {
            float4 qv[4], kv4[4];
#pragma unroll
            for (int i = 0; i < 4; i++) qv[i]  = *(const float4*)(Qs + (ty*4+i)*SD + d);
#pragma unroll
            for (int j = 0; j < 4; j++) kv4[j] = *(const float4*)(Ks + (tx*4+j)*SD + d);
#pragma unroll
            for (int i = 0; i < 4; i++)
#pragma unroll
                for (int j = 0; j < 4; j++)
                    sreg[i][j] += qv[i].x*kv4[j].x + qv[i].y*kv4[j].y
                                + qv[i].z*kv4[j].z + qv[i].w*kv4[j].w;
        }
        // mask + store to Ps
#pragma unroll
        for (int i = 0; i < 4; i++) {
            int r  = ty*4 + i;
            int qg = qt*64 + r;
            int qb = qg >> 4;
            int ap = s_apos[r >> 4];
#pragma unroll
            for (int j = 0; j < 4; j++) {
                int kk = kv0 + tx*4 + j;
                bool vis = (kk < S_) ? (kk < ap) : (((kk - S_) >> 4) == qb);
                Ps[r*PS + tx*4 + j] = vis ? sreg[i][j] : -1e30f;
            }
        }
        __syncthreads();

        // online softmax row update (one thread per row)
        if (t < 64) {
            float m_old = sm_m[t];
            float mt = m_old;
            for (int j = 0; j < 64; j++) mt = fmaxf(mt, Ps[t*PS + j]);
            float c = __expf(m_old - mt);
            float rs = 0.f;
            for (int j = 0; j < 64; j++) {
                float sv = Ps[t*PS + j];
                float p  = (sv < -9e29f) ? 0.f : __expf(sv - mt);
                Ps[t*PS + j] = p;
                rs += p;
            }
            sm_m[t] = mt;
            sm_l[t] = sm_l[t] * c + rs;
            sm_c[t] = c;
        }
        __syncthreads();

        // o update: thread owns rows ty*4..+3, dh tx*8..+7
#pragma unroll
        for (int i = 0; i < 4; i++) {
            float c = sm_c[ty*4 + i];
#pragma unroll
            for (int j = 0; j < 8; j++) acc[i][j] *= c;
        }
        for (int j = 0; j < 64; j++) {
            float4 v0 = *(const float4*)(Vs + j*SD + tx*8);
            float4 v1 = *(const float4*)(Vs + j*SD + tx*8 + 4);
#pragma unroll
            for (int i = 0; i < 4; i++) {
                float p = Ps[(ty*4+i)*PS + j];
                acc[i][0] += p*v0.x; acc[i][1] += p*v0.y;
                acc[i][2] += p*v0.z; acc[i][3] += p*v0.w;
                acc[i][4] += p*v1.x; acc[i][5] += p*v1.y;
                acc[i][6] += p*v1.z; acc[i][7] += p*v1.w;
            }
        }
        __syncthreads();
    }

#pragma unroll
    for (int i = 0; i < 4; i++) {
        int r = ty*4 + i;
        float inv_l = 1.f / sm_l[r];
        size_t ob = ((size_t)b*Q_ + qt*64 + r) * D_ + h*DH_ + tx*8;
        float4 o0 = {acc[i][0]*inv_l, acc[i][1]*inv_l, acc[i][2]*inv_l, acc[i][3]*inv_l};
        float4 o1 = {acc[i][4]*inv_l, acc[i][5]*inv_l, acc[i][6]*inv_l, acc[i][7]*inv_l};
        *(float4*)(o + ob)     = o0;
        *(float4*)(o + ob + 4) = o1;
    }
}

// ---------------- hidden = rmsnorm(emb + oproj) * norm_weight ----------------
__global__ void k_addnorm(const float* __restrict__ nw) {
    int row = blockIdx.x;
    int t   = threadIdx.x;
    const float* e = g_emb + (size_t)row * D_;
    const float* o = g_op  + (size_t)row * D_;
    float ss = 0.f;
    for (int d = t; d < D_; d += 256) { float h = e[d] + o[d]; ss += h * h; }
    __shared__ float red[256];
    red[t] = ss; __syncthreads();
    for (int st = 128; st; st >>= 1) { if (t < st) red[t] += red[t + st]; __syncthreads(); }
    float inv = rsqrtf(red[0] / (float)D_ + 1e-6f);
    for (int d = t; d < D_; d += 256)
        g_hid[(size_t)row * D_ + d] = (e[d] + o[d]) * inv * nw[d];
}

// ---------------- per-token logsumexp + argmax + nll ----------------
__global__ void k_loss(const int* __restrict__ ids, const int* __restrict__ anc) {
    int row = blockIdx.x;            // 0..2047
    int b = row >> 10, qi = row & 1023;
    int off = qi & 15;
    if (off == 0) {
        if (threadIdx.x == 0) {
            g_part[row*4+0] = 0.f; g_part[row*4+1] = 0.f;
            g_part[row*4+2] = 0.f; g_part[row*4+3] = 0.f;
        }
        return;
    }
    int anchor = anc[b*NA_ + (qi >> 4)];
    int label  = ids[b*S_ + anchor + off];
    const float* L = g_logits + (size_t)row * V_;
    int t = threadIdx.x;
    float m = -1e30f, s = 0.f, bm = -1e30f;
    int bi = 0;
    for (int vv = t; vv < V_; vv += 256) {
        float x = L[vv];
        if (x > m) { s = s * expf(m - x) + 1.f; m = x; }
        else       { s += expf(x - m); }
        if (x > bm || (x == bm && vv < bi)) { bm = x; bi = vv; }
    }
    __shared__ float rm[256], rs[256], rbm[256];
    __shared__ int rbi[256];
    rm[t] = m; rs[t] = s; rbm[t] = bm; rbi[t] = bi;
    __syncthreads();
    for (int st = 128; st; st >>= 1) {
        if (t < st) {
            float m2 = rm[t+st], s2 = rs[t+st];
            float M = fmaxf(rm[t], m2);
            rs[t] = rs[t]*expf(rm[t]-M) + s2*expf(m2-M);
            rm[t] = M;
            float b2 = rbm[t+st]; int i2 = rbi[t+st];
            if (b2 > rbm[t] || (b2 == rbm[t] && i2 < rbi[t])) { rbm[t] = b2; rbi[t] = i2; }
        }
        __syncthreads();
    }
    if (t == 0) {
        float lse = rm[0] + logf(rs[0]);
        float nll = lse - L[label];
        float w   = expf(-(float)(off - 1) / 7.0f);
        g_part[row*4+0] = nll * w;
        g_part[row*4+1] = w;
        g_part[row*4+2] = (rbi[0] == label) ? 1.f : 0.f;
        g_part[row*4+3] = 1.f;
    }
}

// ---------------- final scalar reduction ----------------
__global__ void k_final(float* __restrict__ out) {
    int t = threadIdx.x;
    float a = 0.f, bw = 0.f, c = 0.f, d = 0.f;
    for (int r = t; r < B_*Q_; r += 256) {
        a  += g_part[r*4+0];
        bw += g_part[r*4+1];
        c  += g_part[r*4+2];
        d  += g_part[r*4+3];
    }
    __shared__ float s0[256], s1[256], s2[256], s3[256];
    s0[t]=a; s1[t]=bw; s2[t]=c; s3[t]=d;
    __syncthreads();
    for (int st = 128; st; st >>= 1) {
        if (t < st) { s0[t]+=s0[t+st]; s1[t]+=s1[t+st]; s2[t]+=s2[t+st]; s3[t]+=s3[t+st]; }
        __syncthreads();
    }
    if (t == 0) {
        out[0] = s0[0] / fmaxf(s1[0], 1e-6f);
        out[1] = s2[0] / fmaxf(s3[0], 1.0f);
    }
}

// ---------------- launch ----------------
extern "C" void kernel_launch(void* const* d_in, const int* in_sizes, int n_in,
                              void* d_out, int out_size) {
    const int*   ids     = (const int*)  d_in[0];
    const float* hs      = (const float*)d_in[1];
    // d_in[2] loss_mask — unused by reference
    const float* lm_head = (const float*)d_in[3];
    const float* norm_w  = (const float*)d_in[4];
    const int*   anc     = (const int*)  d_in[5];
    const float* ctx_w   = (const float*)d_in[6];
    const float* embed   = (const float*)d_in[7];
    const float* wq      = (const float*)d_in[8];
    const float* wk      = (const float*)d_in[9];
    const float* wv      = (const float*)d_in[10];
    const float* wo      = (const float*)d_in[11];
    float* out = (float*)d_out;

    void *p;
    cudaGetSymbolAddress(&p, g_ctxcat); float* ctxcat = (float*)p;
    cudaGetSymbolAddress(&p, g_ctx);    float* ctx    = (float*)p;
    cudaGetSymbolAddress(&p, g_emb);    float* emb    = (float*)p;
    cudaGetSymbolAddress(&p, g_xkv);    float* xkv    = (float*)p;
    cudaGetSymbolAddress(&p, g_q);      float* qb     = (float*)p;
    cudaGetSymbolAddress(&p, g_k);      float* kb     = (float*)p;
    cudaGetSymbolAddress(&p, g_v);      float* vb     = (float*)p;
    cudaGetSymbolAddress(&p, g_ao);     float* ao     = (float*)p;
    cudaGetSymbolAddress(&p, g_op);     float* op     = (float*)p;
    cudaGetSymbolAddress(&p, g_hid);    float* hid    = (float*)p;
    cudaGetSymbolAddress(&p, g_logits); float* logits = (float*)p;

    cudaFuncSetAttribute(k_attn, cudaFuncAttributeMaxDynamicSharedMemorySize, ATTN_SMEM);

    // 1. pack ctx_cat
    k_pack_ctxcat<<<(B_*S_*Lh_*D_/4 + 255)/256, 256>>>(hs);
    // 2. embedding gather
    k_emb<<<(B_*Q_*D_/4 + 255)/256, 256>>>(ids, anc, embed);
    // 3. ctx projection (TF32 tensor cores)
    k_mma_nt<<<dim3(D_/BN, B_*S_/BM), 256>>>(ctxcat, ctx_w, ctx, B_*S_, D_, Lh_*D_);
    // 4. x_kv pack
    k_xkv<<<(B_*KV_*D_/4 + 255)/256, 256>>>();
    // 5. q projection + rope
    k_mma_nt<<<dim3(D_/BN, B_*Q_/BM), 256>>>(emb, wq, qb, B_*Q_, D_, D_);
    k_rope<<<(B_*Q_*H_*64 + 255)/256, 256>>>(qb, anc, B_*Q_, 0);
    // 6. k projection + rope
    k_mma_nt<<<dim3(D_/BN, B_*KV_/BM), 256>>>(xkv, wk, kb, B_*KV_, D_, D_);
    k_rope<<<(B_*KV_*H_*64 + 255)/256, 256>>>(kb, anc, B_*KV_, 1);
    // 7. v projection
    k_mma_nt<<<dim3(D_/BN, B_*KV_/BM), 256>>>(xkv, wv, vb, B_*KV_, D_, D_);
    // 8. attention
    k_attn<<<dim3(Q_/64, H_, B_), 256, ATTN_SMEM>>>(qb, kb, vb, anc, ao);
    // 9. output projection
    k_mma_nt<<<dim3(D_/BN, B_*Q_/BM), 256>>>(ao, wo, op, B_*Q_, D_, D_);
    // 10. residual + rmsnorm
    k_addnorm<<<B_*Q_, 256>>>(norm_w);
    // 11. lm_head
    k_mma_nt<<<dim3(V_/BN, B_*Q_/BM), 256>>>(hid, lm_head, logits, B_*Q_, V_, D_);
    // 12. per-token loss
    k_loss<<<B_*Q_, 256>>>(ids, anc);
    // 13. final scalars
    k_final<<<1, 256>>>(out);
}